// round 1
// baseline (speedup 1.0000x reference)
#include <cuda_runtime.h>

// Shapes fixed by the problem: B=16, N=64, D=256, E=256
// Inputs (metadata order): nodes, edges, W_in, b_in, W_coef, b_coef, W_out, b_out, B, N
// Output: concat(new_nodes[1024*256], h[65536*256]) as float32.

#define NROWS   1024          // B*N
#define D_      256
#define OUT_H_OFF (NROWS * D_)   // 262144

// Scratch: P (cols 0..255) = nodes@W1 + b_in ; Q (cols 256..511) = nodes@W2
__device__ float g_PQ[NROWS * 512];

// ---------------------------------------------------------------------------
// Kernel A: PQ = [nodes@W1 + b_in | nodes@W2],  1024 x 512, K=256
// grid (8, 16): blockIdx.x = 64-col block, blockIdx.y = 64-row block
// ---------------------------------------------------------------------------
__global__ __launch_bounds__(256) void precompute_pq(
    const float* __restrict__ nodes,   // [1024, 256]
    const float* __restrict__ W_in,    // [768, 256]
    const float* __restrict__ b_in)    // [256]
{
    __shared__ float As[64 * 68];  // [k][r], row stride 68 (16B-aligned, depadded banks)
    __shared__ float Bs[64 * 64];  // [k][c]

    const int tid = threadIdx.x;
    const int cb  = blockIdx.x;            // 0..7 (cols of PQ in 64-blocks)
    const int rb  = blockIdx.y;            // 0..15
    const int kadd  = (cb >= 4) ? 256 : 0; // second half uses W_in rows 256..511
    const int cbase = (cb & 3) * 64;       // column within W block
    const int ty = tid >> 4, tx = tid & 15;

    float acc[4][4];
#pragma unroll
    for (int a = 0; a < 4; ++a)
#pragma unroll
        for (int c = 0; c < 4; ++c) acc[a][c] = 0.f;

    for (int kc = 0; kc < 4; ++kc) {
        // A tile: nodes[rb*64 + r][kc*64 + k]  -> As[k][r] (transposed)
#pragma unroll
        for (int u = 0; u < 4; ++u) {
            int t  = tid + u * 256;             // 0..1023
            int r  = t >> 4;
            int k4 = (t & 15) << 2;
            float4 v = *(const float4*)(nodes + (size_t)(rb * 64 + r) * 256 + kc * 64 + k4);
            As[(k4 + 0) * 68 + r] = v.x;
            As[(k4 + 1) * 68 + r] = v.y;
            As[(k4 + 2) * 68 + r] = v.z;
            As[(k4 + 3) * 68 + r] = v.w;
        }
        // B tile: W_in[kadd + kc*64 + k][cbase + c] -> Bs[k][c]
#pragma unroll
        for (int u = 0; u < 4; ++u) {
            int t  = tid + u * 256;
            int k  = t >> 4;
            int c4 = (t & 15) << 2;
            *(float4*)(Bs + k * 64 + c4) =
                *(const float4*)(W_in + (size_t)(kadd + kc * 64 + k) * 256 + cbase + c4);
        }
        __syncthreads();

#pragma unroll 8
        for (int kk = 0; kk < 64; ++kk) {
            float4 av = *(const float4*)(As + kk * 68 + ty * 4);
            float4 bv = *(const float4*)(Bs + kk * 64 + tx * 4);
            float a[4] = {av.x, av.y, av.z, av.w};
            float b[4] = {bv.x, bv.y, bv.z, bv.w};
#pragma unroll
            for (int ri = 0; ri < 4; ++ri)
#pragma unroll
                for (int ci = 0; ci < 4; ++ci)
                    acc[ri][ci] += a[ri] * b[ci];
        }
        __syncthreads();
    }

#pragma unroll
    for (int ri = 0; ri < 4; ++ri) {
        int r = rb * 64 + ty * 4 + ri;
#pragma unroll
        for (int ci = 0; ci < 4; ++ci) {
            int cg = cb * 64 + tx * 4 + ci;
            float v = acc[ri][ci];
            if (cb < 4) v += b_in[cbase + tx * 4 + ci];
            g_PQ[(size_t)r * 512 + cg] = v;
        }
    }
}

// ---------------------------------------------------------------------------
// Kernel B: one CTA per (b,i). Fused: edge GEMM -> h -> coefs -> softmax ->
// residual -> out-row GEMM. 256 threads: 8 warps (j-tiles) x 32 lanes (d-tiles)
// ---------------------------------------------------------------------------
__global__ __launch_bounds__(256) void gnn_main(
    const float* __restrict__ nodes,
    const float* __restrict__ edges,   // [65536, 256]
    const float* __restrict__ W_in,    // [768, 256] (we use rows 512..767 = W3)
    const float* __restrict__ W_coef,  // [256, 1]
    const float* __restrict__ W_out,   // [256, 256]
    const float* __restrict__ b_out,   // [256]
    float* __restrict__ out)
{
    // flat smem: Es[32][64] | Ws[32][256] | coef[64] | res[256]
    // red_s[8][256] overlays Es (used only after the GEMM phase)
    __shared__ float sm[32 * 64 + 32 * 256 + 64 + 256];
    float* Es     = sm;                 // 2048 floats
    float* Ws     = sm + 2048;          // 8192 floats
    float* coef_s = sm + 2048 + 8192;   // 64
    float* res_s  = coef_s + 64;        // 256
    float* red_s  = sm;                 // overlays Es: [8][256]

    const int bid = blockIdx.x;         // b*64 + i
    const int b   = bid >> 6;
    const int i   = bid & 63;
    const int tid = threadIdx.x;
    const int tj  = tid >> 5;           // warp id: j-rows tj*8..tj*8+7
    const int td  = tid & 31;           // lane: d-cols td*8..td*8+7
    const int J0  = tj * 8;
    const int D0  = td * 8;

    const float* Ebase = edges + (size_t)bid * 64 * 256;
    const float* W3    = W_in + (size_t)512 * 256;

    float acc[8][8];
#pragma unroll
    for (int jr = 0; jr < 8; ++jr)
#pragma unroll
        for (int dd = 0; dd < 8; ++dd) acc[jr][dd] = 0.f;

    // ---- edge GEMM: H[64][256] += E[64][256] @ W3[256][256], K in chunks of 32
    for (int kc = 0; kc < 8; ++kc) {
        // Es[k][j]  (transposed load of E[j][k])
#pragma unroll
        for (int u = 0; u < 2; ++u) {
            int t  = tid * 2 + u;         // 0..511
            int j  = t >> 3;
            int k4 = (t & 7) << 2;
            float4 v = *(const float4*)(Ebase + (size_t)j * 256 + kc * 32 + k4);
            Es[(k4 + 0) * 64 + j] = v.x;
            Es[(k4 + 1) * 64 + j] = v.y;
            Es[(k4 + 2) * 64 + j] = v.z;
            Es[(k4 + 3) * 64 + j] = v.w;
        }
        // Ws[k][d]
#pragma unroll
        for (int q = 0; q < 8; ++q) {
            int t = tid + q * 256;        // 0..2047
            int k = t >> 6;
            int c = (t & 63) << 2;
            *(float4*)(Ws + k * 256 + c) =
                *(const float4*)(W3 + (size_t)(kc * 32 + k) * 256 + c);
        }
        __syncthreads();

#pragma unroll 4
        for (int kk = 0; kk < 32; ++kk) {
            float4 e0 = *(const float4*)(Es + kk * 64 + J0);
            float4 e1 = *(const float4*)(Es + kk * 64 + J0 + 4);
            float4 w0 = *(const float4*)(Ws + kk * 256 + D0);
            float4 w1 = *(const float4*)(Ws + kk * 256 + D0 + 4);
            float ev[8] = {e0.x, e0.y, e0.z, e0.w, e1.x, e1.y, e1.z, e1.w};
            float wv[8] = {w0.x, w0.y, w0.z, w0.w, w1.x, w1.y, w1.z, w1.w};
#pragma unroll
            for (int jr = 0; jr < 8; ++jr)
#pragma unroll
                for (int dd = 0; dd < 8; ++dd)
                    acc[jr][dd] += ev[jr] * wv[dd];
        }
        __syncthreads();
    }

    // ---- epilogue: h = relu(acc + P_i + Q_j), store h, coef = h @ W_coef
    float p[8], wc[8];
    {
        float4 p0 = *(const float4*)(g_PQ + (size_t)bid * 512 + D0);
        float4 p1 = *(const float4*)(g_PQ + (size_t)bid * 512 + D0 + 4);
        p[0]=p0.x; p[1]=p0.y; p[2]=p0.z; p[3]=p0.w;
        p[4]=p1.x; p[5]=p1.y; p[6]=p1.z; p[7]=p1.w;
        float4 c0 = *(const float4*)(W_coef + D0);
        float4 c1 = *(const float4*)(W_coef + D0 + 4);
        wc[0]=c0.x; wc[1]=c0.y; wc[2]=c0.z; wc[3]=c0.w;
        wc[4]=c1.x; wc[5]=c1.y; wc[6]=c1.z; wc[7]=c1.w;
    }

    float* hout = out + OUT_H_OFF + (size_t)bid * 64 * 256;
    float cpart[8];

#pragma unroll
    for (int jr = 0; jr < 8; ++jr) {
        int j = J0 + jr;
        const float* Qp = g_PQ + (size_t)((b << 6) + j) * 512 + 256 + D0;
        float4 q0 = *(const float4*)(Qp);
        float4 q1 = *(const float4*)(Qp + 4);
        float qv[8] = {q0.x, q0.y, q0.z, q0.w, q1.x, q1.y, q1.z, q1.w};
        float cp = 0.f;
        float hv[8];
#pragma unroll
        for (int dd = 0; dd < 8; ++dd) {
            float h = acc[jr][dd] + p[dd] + qv[dd];
            h = fmaxf(h, 0.f);
            acc[jr][dd] = h;        // keep for residual
            hv[dd] = h;
            cp += h * wc[dd];
        }
        *(float4*)(hout + (size_t)j * 256 + D0)     = make_float4(hv[0], hv[1], hv[2], hv[3]);
        *(float4*)(hout + (size_t)j * 256 + D0 + 4) = make_float4(hv[4], hv[5], hv[6], hv[7]);
        // warp-reduce cp over the 32 d-lanes
#pragma unroll
        for (int off = 16; off; off >>= 1)
            cp += __shfl_xor_sync(0xFFFFFFFFu, cp, off);
        cpart[jr] = cp;
    }
    if (td == 0) {
#pragma unroll
        for (int jr = 0; jr < 8; ++jr) coef_s[J0 + jr] = cpart[jr];
    }
    __syncthreads();

    // ---- softmax over j (diag masked); b_coef is softmax-invariant, skipped
    float m = -3.0e38f;
#pragma unroll 8
    for (int j = 0; j < 64; ++j) {
        float c = coef_s[j] - ((j == i) ? 1e9f : 0.f);
        m = fmaxf(m, c);
    }
    float ssum = 0.f;
#pragma unroll 8
    for (int j = 0; j < 64; ++j) {
        float c = coef_s[j] - ((j == i) ? 1e9f : 0.f);
        ssum += __expf(c - m);
    }
    float inv = 1.f / ssum;

    // ---- residual[d] = sum_j attn[j] * h[j][d]
    float rp[8];
#pragma unroll
    for (int dd = 0; dd < 8; ++dd) rp[dd] = 0.f;
#pragma unroll
    for (int jr = 0; jr < 8; ++jr) {
        int j = J0 + jr;
        float c = coef_s[j] - ((j == i) ? 1e9f : 0.f);
        float a = __expf(c - m) * inv;
#pragma unroll
        for (int dd = 0; dd < 8; ++dd) rp[dd] += a * acc[jr][dd];
    }
    __syncthreads();   // all reads of Es/coef done before red_s overlay is written

    *(float4*)(red_s + tj * 256 + D0)     = make_float4(rp[0], rp[1], rp[2], rp[3]);
    *(float4*)(red_s + tj * 256 + D0 + 4) = make_float4(rp[4], rp[5], rp[6], rp[7]);
    __syncthreads();

    {
        float r = 0.f;
#pragma unroll
        for (int w = 0; w < 8; ++w) r += red_s[w * 256 + tid];
        res_s[tid] = r;
    }
    __syncthreads();

    // ---- new_nodes[i][d] = nodes[i][d] + relu(res @ W_out + b_out), d = tid
    float acc2 = b_out[tid];
#pragma unroll 8
    for (int k = 0; k < 256; ++k)
        acc2 += res_s[k] * W_out[(size_t)k * 256 + tid];
    out[(size_t)bid * 256 + tid] = nodes[(size_t)bid * 256 + tid] + fmaxf(acc2, 0.f);
}

// ---------------------------------------------------------------------------
extern "C" void kernel_launch(void* const* d_in, const int* in_sizes, int n_in,
                              void* d_out, int out_size) {
    const float* nodes  = (const float*)d_in[0];
    const float* edges  = (const float*)d_in[1];
    const float* W_in   = (const float*)d_in[2];
    const float* b_in   = (const float*)d_in[3];
    const float* W_coef = (const float*)d_in[4];
    // d_in[5] = b_coef: constant shift inside softmax -> no-op, skipped
    const float* W_out  = (const float*)d_in[6];
    const float* b_out  = (const float*)d_in[7];
    float* out = (float*)d_out;

    precompute_pq<<<dim3(8, 16), 256>>>(nodes, W_in, b_in);
    gnn_main<<<1024, 256>>>(nodes, edges, W_in, W_coef, W_out, b_out, out);
}

// round 3
// speedup vs baseline: 1.9245x; 1.9245x over previous
#include <cuda_runtime.h>
#include <cstdint>

// Shapes fixed: B=16, N=64, D=E=256. Output: [new_nodes 1024x256 | h 65536x256] f32.
#define NROWS     1024
#define OUT_H_OFF (NROWS * 256)

// ---------------- device scratch ----------------
__device__ float g_PQ[NROWS * 512];    // P = nodes@W1 + b_in | Q = nodes@W2
__device__ float g_W3T[256 * 256];     // W3 transposed: [n][k]
__device__ float g_res[NROWS * 256];   // attn-weighted residual

// ---------------- helpers ----------------
__device__ __forceinline__ uint32_t f2tf32(float f) {
    uint32_t u;
    asm("cvt.rna.tf32.f32 %0, %1;" : "=r"(u) : "f"(f));
    return u;
}
__device__ __forceinline__ void mma_tf32(float* c, const uint32_t* a, const uint32_t* b) {
    asm volatile(
        "mma.sync.aligned.m16n8k8.row.col.f32.tf32.tf32.f32 "
        "{%0,%1,%2,%3}, {%4,%5,%6,%7}, {%8,%9}, {%0,%1,%2,%3};"
        : "+f"(c[0]), "+f"(c[1]), "+f"(c[2]), "+f"(c[3])
        : "r"(a[0]), "r"(a[1]), "r"(a[2]), "r"(a[3]), "r"(b[0]), "r"(b[1]));
}

// ---------------- smem layout for gnn_main3 (bytes) ----------------
#define ECH_OFF   0        // [64][36] f = 9216
#define WCH_OFF   9216     // [256][36] f = 36864 -> ends 46080
#define HS_OFF    0        // epilogue overlay: [64][260] f = 66560
#define PS_OFF    66560    // 256 f
#define WCS_OFF   67584    // 256 f
#define CP_OFF    68608    // [4][64] f
#define COEF_OFF  69632    // 64 f
#define ATTN_OFF  69888    // 64 f
#define SMEM_BYTES 70400

// ===========================================================================
// Kernel A: PQ = [nodes@W1 + b_in | nodes@W2], 1024x512, K=256. grid (8,16)x256
// ===========================================================================
__global__ __launch_bounds__(256) void precompute_pq(
    const float* __restrict__ nodes, const float* __restrict__ W_in, const float* __restrict__ b_in)
{
    __shared__ float As[64 * 68];
    __shared__ float Bs[64 * 64];
    const int tid = threadIdx.x;
    const int cb = blockIdx.x, rb = blockIdx.y;
    const int kadd = (cb >= 4) ? 256 : 0;
    const int cbase = (cb & 3) * 64;
    const int ty = tid >> 4, tx = tid & 15;

    float acc[4][4];
#pragma unroll
    for (int a = 0; a < 4; ++a)
#pragma unroll
        for (int c = 0; c < 4; ++c) acc[a][c] = 0.f;

    for (int kc = 0; kc < 4; ++kc) {
#pragma unroll
        for (int u = 0; u < 4; ++u) {
            int t = tid + u * 256, r = t >> 4, k4 = (t & 15) << 2;
            float4 v = *(const float4*)(nodes + (size_t)(rb * 64 + r) * 256 + kc * 64 + k4);
            As[(k4 + 0) * 68 + r] = v.x; As[(k4 + 1) * 68 + r] = v.y;
            As[(k4 + 2) * 68 + r] = v.z; As[(k4 + 3) * 68 + r] = v.w;
        }
#pragma unroll
        for (int u = 0; u < 4; ++u) {
            int t = tid + u * 256, k = t >> 4, c4 = (t & 15) << 2;
            *(float4*)(Bs + k * 64 + c4) =
                *(const float4*)(W_in + (size_t)(kadd + kc * 64 + k) * 256 + cbase + c4);
        }
        __syncthreads();
#pragma unroll 8
        for (int kk = 0; kk < 64; ++kk) {
            float4 av = *(const float4*)(As + kk * 68 + ty * 4);
            float4 bv = *(const float4*)(Bs + kk * 64 + tx * 4);
            float a[4] = {av.x, av.y, av.z, av.w}, b[4] = {bv.x, bv.y, bv.z, bv.w};
#pragma unroll
            for (int ri = 0; ri < 4; ++ri)
#pragma unroll
                for (int ci = 0; ci < 4; ++ci) acc[ri][ci] += a[ri] * b[ci];
        }
        __syncthreads();
    }
#pragma unroll
    for (int ri = 0; ri < 4; ++ri) {
        int r = rb * 64 + ty * 4 + ri;
#pragma unroll
        for (int ci = 0; ci < 4; ++ci) {
            int cg = cb * 64 + tx * 4 + ci;
            float v = acc[ri][ci];
            if (cb < 4) v += b_in[cbase + tx * 4 + ci];
            g_PQ[(size_t)r * 512 + cg] = v;
        }
    }
}

// ===========================================================================
// Kernel A2: transpose W3 (W_in rows 512..767) -> g_W3T [n][k]. grid (8,8)x256
// ===========================================================================
__global__ __launch_bounds__(256) void transpose_w3(const float* __restrict__ W_in)
{
    __shared__ float t[32][33];
    const float* W3 = W_in + (size_t)512 * 256;
    int bx = blockIdx.x, by = blockIdx.y;
    int tx = threadIdx.x & 31, ty = threadIdx.x >> 5;
#pragma unroll
    for (int u = 0; u < 32; u += 8)
        t[ty + u][tx] = W3[(size_t)(by * 32 + ty + u) * 256 + bx * 32 + tx];
    __syncthreads();
#pragma unroll
    for (int u = 0; u < 32; u += 8)
        g_W3T[(size_t)(bx * 32 + ty + u) * 256 + by * 32 + tx] = t[tx][ty + u];
}

// ===========================================================================
// Kernel B: mma.sync tf32 GEMM (H = E@W3 per (b,i)) + fused attention.
// grid 1024, 256 threads = 8 warps: mw = wid>>2 (2 m-tiles), nw = wid&3 (4 n-tiles)
// Warp tile: 32 rows x 64 cols; per k8 step: 2 A-frags, 8 B-frags, 16 mmas.
// ===========================================================================
__global__ __launch_bounds__(256) void gnn_main3(
    const float* __restrict__ edges,
    const float* __restrict__ W_coef,
    float* __restrict__ out)
{
    extern __shared__ char sm[];
    float* Ech  = (float*)(sm + ECH_OFF);    // [64][36]
    float* Wch  = (float*)(sm + WCH_OFF);    // [256][36]
    float* hs   = (float*)(sm + HS_OFF);     // [64][260] (overlay after GEMM)
    float* ps   = (float*)(sm + PS_OFF);
    float* wcs  = (float*)(sm + WCS_OFF);
    float* cp   = (float*)(sm + CP_OFF);     // [4][64]
    float* coef_s = (float*)(sm + COEF_OFF);
    float* attn_s = (float*)(sm + ATTN_OFF);

    const int tid = threadIdx.x;
    const int wid = tid >> 5;
    const int l   = tid & 31;
    const int mw  = wid >> 2;        // 0..1
    const int nw  = wid & 3;         // 0..3
    const int rg  = l >> 2;          // 0..7
    const int tg  = l & 3;           // 0..3
    const int bid = blockIdx.x;      // b*64 + i
    const int b64 = (bid >> 6) << 6;
    const int i_g = bid & 63;

    // Preload P row (this i) and W_coef into smem (regions disjoint from Ech/Wch)
    ps[tid]  = g_PQ[(size_t)bid * 512 + tid];
    wcs[tid] = W_coef[tid];

    float acc[2][8][4];
#pragma unroll
    for (int mt = 0; mt < 2; ++mt)
#pragma unroll
        for (int nt = 0; nt < 8; ++nt)
#pragma unroll
            for (int q = 0; q < 4; ++q) acc[mt][nt][q] = 0.f;

    const float* Ebase = edges + (size_t)bid * 64 * 256;

    // ---- K loop: 8 chunks of 32 ----
    for (int ch = 0; ch < 8; ++ch) {
        // Ech[r][k] = E[r][ch*32+k], stride 36
#pragma unroll
        for (int u = 0; u < 2; ++u) {
            int idx = tid * 2 + u;                 // 0..511 float4s
            int r = idx >> 3, k4 = (idx & 7) << 2;
            float4 v = *(const float4*)(Ebase + (size_t)r * 256 + ch * 32 + k4);
            *(float4*)(Ech + r * 36 + k4) = v;
        }
        // Wch[n][k] = W3T[n][ch*32+k], stride 36
#pragma unroll
        for (int u = 0; u < 8; ++u) {
            int idx = tid + u * 256;               // 0..2047 float4s
            int n = idx >> 3, k4 = (idx & 7) << 2;
            float4 v = *(const float4*)(g_W3T + (size_t)n * 256 + ch * 32 + k4);
            *(float4*)(Wch + n * 36 + k4) = v;
        }
        __syncthreads();

#pragma unroll
        for (int k8 = 0; k8 < 4; ++k8) {
            const int kb = k8 * 8;
            uint32_t a[2][4], b[8][2];
#pragma unroll
            for (int mt = 0; mt < 2; ++mt) {
                int r0 = mw * 32 + mt * 16 + rg;
                a[mt][0] = f2tf32(Ech[r0 * 36 + kb + tg]);
                a[mt][1] = f2tf32(Ech[(r0 + 8) * 36 + kb + tg]);
                a[mt][2] = f2tf32(Ech[r0 * 36 + kb + 4 + tg]);
                a[mt][3] = f2tf32(Ech[(r0 + 8) * 36 + kb + 4 + tg]);
            }
#pragma unroll
            for (int nt = 0; nt < 8; ++nt) {
                int n0 = nw * 64 + nt * 8 + rg;
                b[nt][0] = f2tf32(Wch[n0 * 36 + kb + tg]);
                b[nt][1] = f2tf32(Wch[n0 * 36 + kb + 4 + tg]);
            }
#pragma unroll
            for (int mt = 0; mt < 2; ++mt)
#pragma unroll
                for (int nt = 0; nt < 8; ++nt)
                    mma_tf32(acc[mt][nt], a[mt], b[nt]);
        }
        __syncthreads();
    }

    // ---- epilogue: h = relu(acc + P_i + Q_j) -> hs (overlay Ech/Wch) ----
#pragma unroll
    for (int mt = 0; mt < 2; ++mt) {
        int rA = mw * 32 + mt * 16 + rg;
        int rB = rA + 8;
        const float* qA = g_PQ + (size_t)(b64 + rA) * 512 + 256;
        const float* qB = g_PQ + (size_t)(b64 + rB) * 512 + 256;
#pragma unroll
        for (int nt = 0; nt < 8; ++nt) {
            int c0 = nw * 64 + nt * 8 + tg * 2;
            float2 pv = *(const float2*)(ps + c0);
            float2 qa = *(const float2*)(qA + c0);
            float2 qb = *(const float2*)(qB + c0);
            float h0 = fmaxf(acc[mt][nt][0] + pv.x + qa.x, 0.f);
            float h1 = fmaxf(acc[mt][nt][1] + pv.y + qa.y, 0.f);
            float h2 = fmaxf(acc[mt][nt][2] + pv.x + qb.x, 0.f);
            float h3 = fmaxf(acc[mt][nt][3] + pv.y + qb.y, 0.f);
            *(float2*)(hs + rA * 260 + c0) = make_float2(h0, h1);
            *(float2*)(hs + rB * 260 + c0) = make_float2(h2, h3);
        }
    }
    __syncthreads();

    // ---- h -> gmem (coalesced float4) ----
    float* hout = out + OUT_H_OFF + (size_t)bid * 64 * 256;
    {
#pragma unroll
        for (int rr = wid * 8; rr < wid * 8 + 8; ++rr) {
#pragma unroll
            for (int q = 0; q < 2; ++q) {
                float4 v = *(const float4*)(hs + rr * 260 + q * 128 + l * 4);
                *(float4*)(hout + (size_t)rr * 256 + q * 128 + l * 4) = v;
            }
        }
    }

    // ---- coef[j] = sum_d h[j][d] * wc[d] (4 partial segments) ----
    {
        int j = tid & 63, seg = tid >> 6;
        float s = 0.f;
#pragma unroll 8
        for (int d = 0; d < 64; ++d)
            s += hs[j * 260 + seg * 64 + d] * wcs[seg * 64 + d];
        cp[seg * 64 + j] = s;
    }
    __syncthreads();
    if (tid < 64)
        coef_s[tid] = cp[tid] + cp[64 + tid] + cp[128 + tid] + cp[192 + tid]
                    - ((tid == i_g) ? 1e9f : 0.f);
    __syncthreads();

    // ---- softmax (redundant max, then attn_s) ----
    float mval = -3.0e38f;
#pragma unroll 8
    for (int j = 0; j < 64; ++j) mval = fmaxf(mval, coef_s[j]);
    if (tid < 64) attn_s[tid] = __expf(coef_s[tid] - mval);
    __syncthreads();

    float ssum = 0.f;
#pragma unroll 8
    for (int j = 0; j < 64; ++j) ssum += attn_s[j];
    float inv = 1.f / ssum;

    // ---- residual[d] = sum_j attn[j] * h[j][d], d = tid ----
    {
        float r = 0.f;
#pragma unroll 8
        for (int j = 0; j < 64; ++j)
            r += attn_s[j] * hs[j * 260 + tid];
        g_res[(size_t)bid * 256 + tid] = r * inv;
    }
}

// ===========================================================================
// Kernel C: new_nodes = nodes + relu(g_res @ W_out + b_out). grid (4,16)x256
// ===========================================================================
__global__ __launch_bounds__(256) void finalize(
    const float* __restrict__ nodes, const float* __restrict__ W_out,
    const float* __restrict__ b_out, float* __restrict__ out)
{
    __shared__ float As[64 * 68];
    __shared__ float Bs[64 * 64];
    const int tid = threadIdx.x;
    const int cb = blockIdx.x, rb = blockIdx.y;
    const int cbase = cb * 64;
    const int ty = tid >> 4, tx = tid & 15;

    float acc[4][4];
#pragma unroll
    for (int a = 0; a < 4; ++a)
#pragma unroll
        for (int c = 0; c < 4; ++c) acc[a][c] = 0.f;

    for (int kc = 0; kc < 4; ++kc) {
#pragma unroll
        for (int u = 0; u < 4; ++u) {
            int t = tid + u * 256, r = t >> 4, k4 = (t & 15) << 2;
            float4 v = *(const float4*)(g_res + (size_t)(rb * 64 + r) * 256 + kc * 64 + k4);
            As[(k4 + 0) * 68 + r] = v.x; As[(k4 + 1) * 68 + r] = v.y;
            As[(k4 + 2) * 68 + r] = v.z; As[(k4 + 3) * 68 + r] = v.w;
        }
#pragma unroll
        for (int u = 0; u < 4; ++u) {
            int t = tid + u * 256, k = t >> 4, c4 = (t & 15) << 2;
            *(float4*)(Bs + k * 64 + c4) =
                *(const float4*)(W_out + (size_t)(kc * 64 + k) * 256 + cbase + c4);
        }
        __syncthreads();
#pragma unroll 8
        for (int kk = 0; kk < 64; ++kk) {
            float4 av = *(const float4*)(As + kk * 68 + ty * 4);
            float4 bv = *(const float4*)(Bs + kk * 64 + tx * 4);
            float a[4] = {av.x, av.y, av.z, av.w}, b[4] = {bv.x, bv.y, bv.z, bv.w};
#pragma unroll
            for (int ri = 0; ri < 4; ++ri)
#pragma unroll
                for (int ci = 0; ci < 4; ++ci) acc[ri][ci] += a[ri] * b[ci];
        }
        __syncthreads();
    }
#pragma unroll
    for (int ri = 0; ri < 4; ++ri) {
        int r = rb * 64 + ty * 4 + ri;
#pragma unroll
        for (int ci = 0; ci < 4; ++ci) {
            int cg = cbase + tx * 4 + ci;
            float v = acc[ri][ci] + b_out[cg];
            out[(size_t)r * 256 + cg] = nodes[(size_t)r * 256 + cg] + fmaxf(v, 0.f);
        }
    }
}

// ===========================================================================
extern "C" void kernel_launch(void* const* d_in, const int* in_sizes, int n_in,
                              void* d_out, int out_size) {
    const float* nodes  = (const float*)d_in[0];
    const float* edges  = (const float*)d_in[1];
    const float* W_in   = (const float*)d_in[2];
    const float* b_in   = (const float*)d_in[3];
    const float* W_coef = (const float*)d_in[4];
    // d_in[5] = b_coef: softmax-invariant, skipped
    const float* W_out  = (const float*)d_in[6];
    const float* b_out  = (const float*)d_in[7];
    float* out = (float*)d_out;

    static int smem_set = 0;
    if (!smem_set) {
        cudaFuncSetAttribute(gnn_main3, cudaFuncAttributeMaxDynamicSharedMemorySize, SMEM_BYTES);
        smem_set = 1;
    }

    transpose_w3<<<dim3(8, 8), 256>>>(W_in);
    precompute_pq<<<dim3(8, 16), 256>>>(nodes, W_in, b_in);
    gnn_main3<<<1024, 256, SMEM_BYTES>>>(edges, W_coef, out);
    finalize<<<dim3(4, 16), 256>>>(nodes, W_out, b_out, out);
}